// round 10
// baseline (speedup 1.0000x reference)
#include <cuda_runtime.h>
#include <cuda_bf16.h>
#include <stdint.h>

#define TD 2048
#define BD 8
#define CD 192
#define NC (BD*CD)   // 1536

#define F_PI 3.14159274101257324f

// ---------------- static device scratch ----------------
__device__ __align__(256) __nv_bfloat16 g_Ch [TD*TD];
__device__ __align__(256) __nv_bfloat16 g_Cl [TD*TD];
__device__ __align__(256) __nv_bfloat16 g_CTh[TD*TD];
__device__ __align__(256) __nv_bfloat16 g_CTl[TD*TD];
__device__ __align__(256) __nv_bfloat16 g_Uh [TD*NC];
__device__ __align__(256) __nv_bfloat16 g_Ul [TD*NC];
__device__ __align__(256) __nv_bfloat16 g_Sh [TD*NC];
__device__ __align__(256) __nv_bfloat16 g_Sl [TD*NC];
__device__ __align__(256) float g_Z [TD*NC];
__device__ __align__(256) float g_U2[TD*NC];
__device__ __align__(256) float g_G [TD*NC];
__device__ __align__(256) float g_dk[TD*CD];

// ---------------- helpers ----------------
__device__ __forceinline__ void split_store(float v, __nv_bfloat16* H, __nv_bfloat16* L, size_t idx){
    __nv_bfloat16 h = __float2bfloat16(v);
    H[idx] = h;
    L[idx] = __float2bfloat16(v - __bfloat162float(h));
}

__device__ __forceinline__ uint32_t smem_u32(const void* p){
    return (uint32_t)__cvta_generic_to_shared(p);
}

__device__ __forceinline__ void cpa16(uint32_t saddr, const void* gptr){
    asm volatile("cp.async.cg.shared.global [%0], [%1], 16;" :: "r"(saddr), "l"(gptr));
}
#define CP_COMMIT() asm volatile("cp.async.commit_group;" ::: "memory")
#define CP_WAIT0()  asm volatile("cp.async.wait_group 0;" ::: "memory")

__device__ __forceinline__ void ldm_x4(uint32_t* r, uint32_t a){
    asm volatile("ldmatrix.sync.aligned.m8n8.x4.shared.b16 {%0,%1,%2,%3}, [%4];"
        : "=r"(r[0]), "=r"(r[1]), "=r"(r[2]), "=r"(r[3]) : "r"(a));
}
__device__ __forceinline__ void ldm_x2t(uint32_t* r, uint32_t a){
    asm volatile("ldmatrix.sync.aligned.m8n8.x2.trans.shared.b16 {%0,%1}, [%2];"
        : "=r"(r[0]), "=r"(r[1]) : "r"(a));
}
__device__ __forceinline__ void mma_bf16(float* c, const uint32_t* a, const uint32_t* b){
    asm volatile("mma.sync.aligned.m16n8k16.row.col.f32.bf16.bf16.f32 "
        "{%0,%1,%2,%3}, {%4,%5,%6,%7}, {%8,%9}, {%0,%1,%2,%3};"
        : "+f"(c[0]), "+f"(c[1]), "+f"(c[2]), "+f"(c[3])
        : "r"(a[0]), "r"(a[1]), "r"(a[2]), "r"(a[3]), "r"(b[0]), "r"(b[1]));
}

// ---------------- DCT-II map (matches jax fp32 rounding order) ----------------
__global__ void k_init_cos(){
    int idx = blockIdx.x * blockDim.x + threadIdx.x;
    int n = idx >> 11, t = idx & 2047;
    float wx = ((float)t + 0.5f) * (1.0f / (float)TD);
    float arg = ((float)n * wx) * F_PI;
    float s = (n == 0) ? (0.03125f * 0.70710678118654752f) : 0.03125f;
    float w = cosf(arg) * s;
    split_store(w, g_Ch, g_Cl, (size_t)idx);
}

// 32x32 tiled transpose: CT[t][n] = Cos[n][t] (both hi and lo planes)
__global__ void k_transpose(){
    __shared__ __nv_bfloat16 th[32][33];
    __shared__ __nv_bfloat16 tl[32][33];
    int bx = blockIdx.x * 32, by = blockIdx.y * 32;
    int tx = threadIdx.x, ty = threadIdx.y;
    int x = bx + tx;
    #pragma unroll
    for (int i = 0; i < 32; i += 8){
        size_t gi = (size_t)(by + ty + i) * TD + x;
        th[ty + i][tx] = g_Ch[gi];
        tl[ty + i][tx] = g_Cl[gi];
    }
    __syncthreads();
    int xo = by + tx;
    #pragma unroll
    for (int i = 0; i < 32; i += 8){
        size_t go = (size_t)(bx + ty + i) * TD + xo;
        g_CTh[go] = th[tx][ty + i];
        g_CTl[go] = tl[tx][ty + i];
    }
}

__global__ void k_init_dk(const float* __restrict__ kvec){
    int idx = blockIdx.x * blockDim.x + threadIdx.x;   // TD*CD
    int n = idx / CD, c = idx - n * CD;
    float wn = (float)n * (F_PI / 2048.0f);
    float d = expf(-wn * wn);
    g_dk[idx] = powf(d, kvec[c]);
}

// ---------------- front: dwconv -> grouped conv -> split u, z (smem-tiled) ----
// Block: one batch b, one 32-step time strip. Stage 1 computes h1 once into
// smem (36 rows = strip + 2-halo each side); stage 2 derives u,z from smem.
#define FT 32
__global__ void __launch_bounds__(256) k_front(
        const float* __restrict__ x,  const float* __restrict__ dw,
        const float* __restrict__ db, const float* __restrict__ lw,
        const float* __restrict__ lb){
    __shared__ float s_h1[FT + 4][CD];          // 36 x 192
    __shared__ float s_dw[CD*3], s_db[CD];
    __shared__ float s_lw[2*CD*3], s_lb[2*CD];

    int tid = threadIdx.x;
    int t0  = blockIdx.x * FT;
    int b   = blockIdx.y;

    // load weights into smem
    for (int i = tid; i < CD*3;   i += 256) s_dw[i] = dw[i];
    for (int i = tid; i < CD;     i += 256) s_db[i] = db[i];
    for (int i = tid; i < 2*CD*3; i += 256) s_lw[i] = lw[i];
    for (int i = tid; i < 2*CD;   i += 256) s_lb[i] = lb[i];
    __syncthreads();

    // stage 1: h1[tt][cin] for tt in [t0-2, t0+FT+2)
    const float* xb = x + (size_t)b * TD * CD;
    for (int i = tid; i < (FT + 4) * CD; i += 256){
        int r   = i / CD;           // smem row
        int cin = i - r * CD;
        int tt  = t0 - 2 + r;
        float h = 0.f;
        if (tt >= 0 && tt < TD){
            const float* xp = xb + (size_t)tt * CD + cin;
            h = s_db[cin] + xp[0] * s_dw[cin*3 + 1];
            if (tt > 0)      h += xp[-CD] * s_dw[cin*3 + 0];
            if (tt < TD-1)   h += xp[ CD] * s_dw[cin*3 + 2];
        }
        s_h1[r][cin] = h;
    }
    __syncthreads();

    // stage 2: u,z for t in [t0, t0+FT), c in [0,CD)
    for (int i = tid; i < FT * CD; i += 256){
        int dt = i / CD;
        int c  = i - dt * CD;
        int t  = t0 + dt;
        int cu = c >> 1;
        int cz = 96 + cu;           // (CD + c) >> 1

        float u = s_h1[dt+1][cu]*s_lw[c*3+0] + s_h1[dt+2][cu]*s_lw[c*3+1]
                + s_h1[dt+3][cu]*s_lw[c*3+2] + s_lb[c];
        int zc = CD + c;
        float z = s_h1[dt+1][cz]*s_lw[zc*3+0] + s_h1[dt+2][cz]*s_lw[zc*3+1]
                + s_h1[dt+3][cz]*s_lw[zc*3+2] + s_lb[zc];

        size_t o = (size_t)t * NC + (size_t)b * CD + c;
        split_store(u, g_Uh, g_Ul, o);
        g_Z[o] = z;
    }
}

// ---------------- GEMM: C = A@B with bf16 hi/lo 3-product split ----------------
// mode 1: A = Cos,  B = U  -> scale by dk, split-store to g_Sh/g_Sl
// mode 0: A = CosT, B = S  -> fp32 store to g_U2
#define BM 128
#define BN 128
#define BK 16
#define AP (BK + 8)   // 24 halfs / row
#define BP (BN + 8)   // 136 halfs / row
#define KITERS (TD / BK)

__global__ void __launch_bounds__(256) k_gemm(int mode){
    const __nv_bfloat16 *Agh, *Agl, *Bgh, *Bgl;
    if (mode){ Agh = g_Ch;  Agl = g_Cl;  Bgh = g_Uh; Bgl = g_Ul; }
    else     { Agh = g_CTh; Agl = g_CTl; Bgh = g_Sh; Bgl = g_Sl; }
    const int K = TD, N = NC;

    __shared__ __align__(16) __nv_bfloat16 sAh[2][BM][AP];
    __shared__ __align__(16) __nv_bfloat16 sAl[2][BM][AP];
    __shared__ __align__(16) __nv_bfloat16 sBh[2][BK][BP];
    __shared__ __align__(16) __nv_bfloat16 sBl[2][BK][BP];

    int tid  = threadIdx.x;
    int lane = tid & 31, wid = tid >> 5;
    int wm = wid >> 1;           // 0..3  (32-row stripes)
    int wn = wid & 1;            // 0..1  (64-col stripes)
    int bm = blockIdx.y * BM, bn = blockIdx.x * BN;

    float acc[2][8][4];
    #pragma unroll
    for (int i=0;i<2;i++) for (int j=0;j<8;j++) for (int q=0;q<4;q++) acc[i][j][q] = 0.f;

    // per-thread load coords
    int ar = tid >> 1;              // 0..127
    int ac = (tid & 1) << 3;        // 0 or 8
    int br = tid >> 4;              // 0..15
    int bc = (tid & 15) << 3;       // 0..120

    int a_row = lane & 15;
    int a_col = (lane >> 4) << 3;
    int b_row = lane & 15;

    // ---- stage loader ----
    auto load_stage = [&](int s, int kt){
        size_t goA = (size_t)(bm + ar) * K + kt + ac;
        cpa16(smem_u32(&sAh[s][ar][ac]), Agh + goA);
        cpa16(smem_u32(&sAl[s][ar][ac]), Agl + goA);
        size_t goB = (size_t)(kt + br) * N + bn + bc;
        cpa16(smem_u32(&sBh[s][br][bc]), Bgh + goB);
        cpa16(smem_u32(&sBl[s][br][bc]), Bgl + goB);
    };

    load_stage(0, 0);
    CP_COMMIT();

    for (int it = 0; it < KITERS; it++){
        int s = it & 1;
        CP_WAIT0();
        __syncthreads();
        if (it + 1 < KITERS){
            load_stage((it + 1) & 1, (it + 1) * BK);
            CP_COMMIT();
        }

        uint32_t ah[2][4], al[2][4], bh[8][2], bl[8][2];
        #pragma unroll
        for (int mf = 0; mf < 2; mf++){
            int mrow = wm*32 + mf*16 + a_row;
            ldm_x4(ah[mf], smem_u32(&sAh[s][mrow][a_col]));
            ldm_x4(al[mf], smem_u32(&sAl[s][mrow][a_col]));
        }
        #pragma unroll
        for (int nf = 0; nf < 8; nf++){
            int ncol = wn*64 + nf*8;
            ldm_x2t(bh[nf], smem_u32(&sBh[s][b_row][ncol]));
            ldm_x2t(bl[nf], smem_u32(&sBl[s][b_row][ncol]));
        }
        #pragma unroll
        for (int mf = 0; mf < 2; mf++)
            #pragma unroll
            for (int nf = 0; nf < 8; nf++)
                mma_bf16(acc[mf][nf], ah[mf], bh[nf]);
        #pragma unroll
        for (int mf = 0; mf < 2; mf++)
            #pragma unroll
            for (int nf = 0; nf < 8; nf++)
                mma_bf16(acc[mf][nf], al[mf], bh[nf]);
        #pragma unroll
        for (int mf = 0; mf < 2; mf++)
            #pragma unroll
            for (int nf = 0; nf < 8; nf++)
                mma_bf16(acc[mf][nf], ah[mf], bl[nf]);
    }

    // epilogue
    #pragma unroll
    for (int mf = 0; mf < 2; mf++){
        #pragma unroll
        for (int nf = 0; nf < 8; nf++){
            int row = bm + wm*32 + mf*16 + (lane >> 2);
            int col = bn + wn*64 + nf*8 + ((lane & 3) << 1);
            float* cc = acc[mf][nf];
            if (mode){
                int c0 = col % CD, c1 = (col + 1) % CD;
                const float* dk0 = g_dk + (size_t)row * CD;
                const float* dk8 = dk0 + 8 * CD;
                split_store(cc[0] * dk0[c0], g_Sh, g_Sl, (size_t)row*NC + col);
                split_store(cc[1] * dk0[c1], g_Sh, g_Sl, (size_t)row*NC + col + 1);
                split_store(cc[2] * dk8[c0], g_Sh, g_Sl, (size_t)(row+8)*NC + col);
                split_store(cc[3] * dk8[c1], g_Sh, g_Sl, (size_t)(row+8)*NC + col + 1);
            } else {
                g_U2[(size_t)row*NC + col]         = cc[0];
                g_U2[(size_t)row*NC + col + 1]     = cc[1];
                g_U2[(size_t)(row+8)*NC + col]     = cc[2];
                g_U2[(size_t)(row+8)*NC + col + 1] = cc[3];
            }
        }
    }
}

// ---------------- LayerNorm(C) * silu(z) ----------------
__global__ void k_ln(const float* __restrict__ gam, const float* __restrict__ bet){
    int row = blockIdx.x;                 // 0 .. BD*TD-1
    int b = row / TD, t = row - b * TD;
    int c = threadIdx.x;                  // 0 .. 191
    size_t base = (size_t)t * NC + (size_t)b * CD;

    float u = g_U2[base + c];
    float s1 = u, s2 = u * u;
    #pragma unroll
    for (int off = 16; off; off >>= 1){
        s1 += __shfl_xor_sync(0xffffffffu, s1, off);
        s2 += __shfl_xor_sync(0xffffffffu, s2, off);
    }
    __shared__ float sh[12];
    int w = c >> 5;
    if ((c & 31) == 0){ sh[w] = s1; sh[6 + w] = s2; }
    __syncthreads();
    float S1 = 0.f, S2 = 0.f;
    #pragma unroll
    for (int i = 0; i < 6; i++){ S1 += sh[i]; S2 += sh[6 + i]; }
    float mu  = S1 * (1.0f / CD);
    float var = S2 * (1.0f / CD) - mu * mu;
    float rs  = rsqrtf(var + 1e-5f);

    float z = g_Z[base + c];
    float sil = z / (1.f + expf(-z));
    g_G[base + c] = ((u - mu) * rs * gam[c] + bet[c]) * sil;
}

// ---------------- output depthwise conv + transpose to (B,T,C) ----------------
__global__ void k_outconv(const float* __restrict__ ow, const float* __restrict__ ob,
                          float* __restrict__ out){
    int idx = blockIdx.x * blockDim.x + threadIdx.x;  // BD*TD*CD
    int c = idx % CD;
    int tmp = idx / CD;
    int t = tmp % TD, b = tmp / TD;
    size_t bc = (size_t)b * CD + c;

    float a = ob[c] + g_G[(size_t)t * NC + bc] * ow[c*3 + 1];
    if (t > 0)      a += g_G[(size_t)(t-1) * NC + bc] * ow[c*3 + 0];
    if (t < TD-1)   a += g_G[(size_t)(t+1) * NC + bc] * ow[c*3 + 2];
    out[idx] = a;
}

// ---------------- launcher ----------------
extern "C" void kernel_launch(void* const* d_in, const int* in_sizes, int n_in,
                              void* d_out, int out_size){
    const float* x   = (const float*)d_in[0];
    const float* dw  = (const float*)d_in[1];
    const float* db  = (const float*)d_in[2];
    const float* lw  = (const float*)d_in[3];
    const float* lb  = (const float*)d_in[4];
    const float* gam = (const float*)d_in[5];
    const float* bet = (const float*)d_in[6];
    const float* ow  = (const float*)d_in[7];
    const float* ob  = (const float*)d_in[8];
    const float* kv  = (const float*)d_in[9];
    float* out = (float*)d_out;

    k_init_cos<<<(TD*TD)/256, 256>>>();
    {
        dim3 tb(32, 8), tg(TD/32, TD/32);
        k_transpose<<<tg, tb>>>();
    }
    k_init_dk <<<(TD*CD)/256, 256>>>(kv);
    {
        dim3 fg(TD/FT, BD);        // (64, 8)
        k_front<<<fg, 256>>>(x, dw, db, lw, lb);
    }

    dim3 gg(NC/BN, TD/BM);     // (12, 16)
    k_gemm<<<gg, 256>>>(1);    // A = Cos @ U, scale by decay^k, split
    k_gemm<<<gg, 256>>>(0);    // U2 = CosT @ A

    k_ln     <<<BD*TD, CD>>>(gam, bet);
    k_outconv<<<(BD*TD*CD)/256, 256>>>(ow, ob, out);
}

// round 16
// speedup vs baseline: 1.3914x; 1.3914x over previous
#include <cuda_runtime.h>
#include <cuda_bf16.h>
#include <stdint.h>

#define TD 2048
#define BD 8
#define CD 192
#define NC (BD*CD)   // 1536

#define F_PI 3.14159274101257324f

// ---------------- static device scratch ----------------
__device__ __align__(256) __nv_bfloat16 g_Ch [TD*TD];
__device__ __align__(256) __nv_bfloat16 g_Cl [TD*TD];
__device__ __align__(256) __nv_bfloat16 g_CTh[TD*TD];
__device__ __align__(256) __nv_bfloat16 g_CTl[TD*TD];
__device__ __align__(256) __nv_bfloat16 g_Uh [TD*NC];
__device__ __align__(256) __nv_bfloat16 g_Ul [TD*NC];
__device__ __align__(256) __nv_bfloat16 g_Sh [TD*NC];
__device__ __align__(256) __nv_bfloat16 g_Sl [TD*NC];
__device__ __align__(256) float g_Z [TD*NC];
__device__ __align__(256) float g_U2[TD*NC];
__device__ __align__(256) float g_G [TD*NC];
__device__ __align__(256) float g_dk[TD*CD];

// ---------------- helpers ----------------
__device__ __forceinline__ void split_store(float v, __nv_bfloat16* H, __nv_bfloat16* L, size_t idx){
    __nv_bfloat16 h = __float2bfloat16(v);
    H[idx] = h;
    L[idx] = __float2bfloat16(v - __bfloat162float(h));
}

__device__ __forceinline__ uint32_t smem_u32(const void* p){
    return (uint32_t)__cvta_generic_to_shared(p);
}

__device__ __forceinline__ void cpa16(uint32_t saddr, const void* gptr){
    asm volatile("cp.async.cg.shared.global [%0], [%1], 16;" :: "r"(saddr), "l"(gptr));
}
#define CP_COMMIT() asm volatile("cp.async.commit_group;" ::: "memory")
#define CP_WAIT0()  asm volatile("cp.async.wait_group 0;" ::: "memory")

__device__ __forceinline__ void ldm_x4(uint32_t* r, uint32_t a){
    asm volatile("ldmatrix.sync.aligned.m8n8.x4.shared.b16 {%0,%1,%2,%3}, [%4];"
        : "=r"(r[0]), "=r"(r[1]), "=r"(r[2]), "=r"(r[3]) : "r"(a));
}
__device__ __forceinline__ void ldm_x2t(uint32_t* r, uint32_t a){
    asm volatile("ldmatrix.sync.aligned.m8n8.x2.trans.shared.b16 {%0,%1}, [%2];"
        : "=r"(r[0]), "=r"(r[1]) : "r"(a));
}
__device__ __forceinline__ void mma_bf16(float* c, const uint32_t* a, const uint32_t* b){
    asm volatile("mma.sync.aligned.m16n8k16.row.col.f32.bf16.bf16.f32 "
        "{%0,%1,%2,%3}, {%4,%5,%6,%7}, {%8,%9}, {%0,%1,%2,%3};"
        : "+f"(c[0]), "+f"(c[1]), "+f"(c[2]), "+f"(c[3])
        : "r"(a[0]), "r"(a[1]), "r"(a[2]), "r"(a[3]), "r"(b[0]), "r"(b[1]));
}

// ---------------- DCT-II map (matches jax fp32 rounding order) ----------------
__global__ void k_init_cos(){
    int idx = blockIdx.x * blockDim.x + threadIdx.x;
    int n = idx >> 11, t = idx & 2047;
    float wx = ((float)t + 0.5f) * (1.0f / (float)TD);
    float arg = ((float)n * wx) * F_PI;
    float s = (n == 0) ? (0.03125f * 0.70710678118654752f) : 0.03125f;
    float w = cosf(arg) * s;
    split_store(w, g_Ch, g_Cl, (size_t)idx);
}

// 32x32 tiled transpose: CT[t][n] = Cos[n][t] (both hi and lo planes)
__global__ void k_transpose(){
    __shared__ __nv_bfloat16 th[32][33];
    __shared__ __nv_bfloat16 tl[32][33];
    int bx = blockIdx.x * 32, by = blockIdx.y * 32;
    int tx = threadIdx.x, ty = threadIdx.y;
    int x = bx + tx;
    #pragma unroll
    for (int i = 0; i < 32; i += 8){
        size_t gi = (size_t)(by + ty + i) * TD + x;
        th[ty + i][tx] = g_Ch[gi];
        tl[ty + i][tx] = g_Cl[gi];
    }
    __syncthreads();
    int xo = by + tx;
    #pragma unroll
    for (int i = 0; i < 32; i += 8){
        size_t go = (size_t)(bx + ty + i) * TD + xo;
        g_CTh[go] = th[tx][ty + i];
        g_CTl[go] = tl[tx][ty + i];
    }
}

__global__ void k_init_dk(const float* __restrict__ kvec){
    int idx = blockIdx.x * blockDim.x + threadIdx.x;   // TD*CD
    int n = idx / CD, c = idx - n * CD;
    float wn = (float)n * (F_PI / 2048.0f);
    float d = expf(-wn * wn);
    g_dk[idx] = powf(d, kvec[c]);
}

// ---------------- front: dwconv -> grouped conv -> split u, z (smem-tiled) ----
// FT=16 strips -> 1024 CTAs for occupancy; h1 computed once into smem (20-row
// strip incl. 2-halo); weights read directly (tiny, L1-resident).
#define FT 16
__global__ void __launch_bounds__(256) k_front(
        const float* __restrict__ x,  const float* __restrict__ dw,
        const float* __restrict__ db, const float* __restrict__ lw,
        const float* __restrict__ lb){
    __shared__ float s_h1[FT + 4][CD];          // 20 x 192 = 15.4 KB

    int tid = threadIdx.x;
    int t0  = blockIdx.x * FT;
    int b   = blockIdx.y;

    // stage 1: h1[tt][cin] for tt in [t0-2, t0+FT+2)
    const float* xb = x + (size_t)b * TD * CD;
    for (int i = tid; i < (FT + 4) * CD; i += 256){
        int r   = i / CD;           // smem row
        int cin = i - r * CD;
        int tt  = t0 - 2 + r;
        float h = 0.f;
        if (tt >= 0 && tt < TD){
            const float* xp = xb + (size_t)tt * CD + cin;
            h = db[cin] + xp[0] * dw[cin*3 + 1];
            if (tt > 0)      h += xp[-CD] * dw[cin*3 + 0];
            if (tt < TD-1)   h += xp[ CD] * dw[cin*3 + 2];
        }
        s_h1[r][cin] = h;
    }
    __syncthreads();

    // stage 2: u,z for t in [t0, t0+FT), c in [0,CD)
    for (int i = tid; i < FT * CD; i += 256){
        int dt = i / CD;
        int c  = i - dt * CD;
        int t  = t0 + dt;
        int cu = c >> 1;
        int cz = 96 + cu;           // (CD + c) >> 1

        float u = s_h1[dt+1][cu]*lw[c*3+0] + s_h1[dt+2][cu]*lw[c*3+1]
                + s_h1[dt+3][cu]*lw[c*3+2] + lb[c];
        int zc = CD + c;
        float z = s_h1[dt+1][cz]*lw[zc*3+0] + s_h1[dt+2][cz]*lw[zc*3+1]
                + s_h1[dt+3][cz]*lw[zc*3+2] + lb[zc];

        size_t o = (size_t)t * NC + (size_t)b * CD + c;
        split_store(u, g_Uh, g_Ul, o);
        g_Z[o] = z;
    }
}

// ---------------- GEMM: C = A@B with bf16 hi/lo 3-product split ----------------
// (measured-good r8 configuration: BM=128, BN=64, BK=16)
// mode 1: A = Cos,  B = U  -> scale by dk, split-store to g_Sh/g_Sl
// mode 0: A = CosT, B = S  -> fp32 store to g_U2
#define BM 128
#define BN 64
#define BK 16
#define AP (BK + 8)   // 24 halfs / row
#define BP (BN + 8)   // 72 halfs / row
#define KITERS (TD / BK)

__global__ void __launch_bounds__(256) k_gemm(int mode){
    const __nv_bfloat16 *Agh, *Agl, *Bgh, *Bgl;
    if (mode){ Agh = g_Ch;  Agl = g_Cl;  Bgh = g_Uh; Bgl = g_Ul; }
    else     { Agh = g_CTh; Agl = g_CTl; Bgh = g_Sh; Bgl = g_Sl; }
    const int K = TD, N = NC;

    __shared__ __align__(16) __nv_bfloat16 sAh[2][BM][AP];
    __shared__ __align__(16) __nv_bfloat16 sAl[2][BM][AP];
    __shared__ __align__(16) __nv_bfloat16 sBh[2][BK][BP];
    __shared__ __align__(16) __nv_bfloat16 sBl[2][BK][BP];

    int tid  = threadIdx.x;
    int lane = tid & 31, wid = tid >> 5;
    int wm = wid >> 1;           // 0..3  (32-row stripes)
    int wn = wid & 1;            // 0..1  (32-col stripes)
    int bm = blockIdx.y * BM, bn = blockIdx.x * BN;

    float acc[2][4][4];
    #pragma unroll
    for (int i=0;i<2;i++) for (int j=0;j<4;j++) for (int q=0;q<4;q++) acc[i][j][q] = 0.f;

    // per-thread load coords
    int ar = tid >> 1;              // 0..127
    int ac = (tid & 1) << 3;        // 0 or 8
    int br = tid >> 3;              // (only tid<128 used -> 0..15)
    int bc = (tid & 7) << 3;        // 0..56

    int a_row = lane & 15;
    int a_col = (lane >> 4) << 3;
    int b_row = lane & 15;

    // ---- stage loader ----
    auto load_stage = [&](int s, int kt){
        size_t goA = (size_t)(bm + ar) * K + kt + ac;
        cpa16(smem_u32(&sAh[s][ar][ac]), Agh + goA);
        cpa16(smem_u32(&sAl[s][ar][ac]), Agl + goA);
        if (tid < 128){
            size_t goB = (size_t)(kt + br) * N + bn + bc;
            cpa16(smem_u32(&sBh[s][br][bc]), Bgh + goB);
            cpa16(smem_u32(&sBl[s][br][bc]), Bgl + goB);
        }
    };

    load_stage(0, 0);
    CP_COMMIT();

    for (int it = 0; it < KITERS; it++){
        int s = it & 1;
        CP_WAIT0();
        __syncthreads();
        if (it + 1 < KITERS){
            load_stage((it + 1) & 1, (it + 1) * BK);
            CP_COMMIT();
        }

        uint32_t ah[2][4], al[2][4], bh[4][2], bl[4][2];
        #pragma unroll
        for (int mf = 0; mf < 2; mf++){
            int mrow = wm*32 + mf*16 + a_row;
            ldm_x4(ah[mf], smem_u32(&sAh[s][mrow][a_col]));
            ldm_x4(al[mf], smem_u32(&sAl[s][mrow][a_col]));
        }
        #pragma unroll
        for (int nf = 0; nf < 4; nf++){
            int ncol = wn*32 + nf*8;
            ldm_x2t(bh[nf], smem_u32(&sBh[s][b_row][ncol]));
            ldm_x2t(bl[nf], smem_u32(&sBl[s][b_row][ncol]));
        }
        #pragma unroll
        for (int mf = 0; mf < 2; mf++)
            #pragma unroll
            for (int nf = 0; nf < 4; nf++)
                mma_bf16(acc[mf][nf], ah[mf], bh[nf]);
        #pragma unroll
        for (int mf = 0; mf < 2; mf++)
            #pragma unroll
            for (int nf = 0; nf < 4; nf++)
                mma_bf16(acc[mf][nf], al[mf], bh[nf]);
        #pragma unroll
        for (int mf = 0; mf < 2; mf++)
            #pragma unroll
            for (int nf = 0; nf < 4; nf++)
                mma_bf16(acc[mf][nf], ah[mf], bl[nf]);
    }

    // epilogue
    #pragma unroll
    for (int mf = 0; mf < 2; mf++){
        #pragma unroll
        for (int nf = 0; nf < 4; nf++){
            int row = bm + wm*32 + mf*16 + (lane >> 2);
            int col = bn + wn*32 + nf*8 + ((lane & 3) << 1);
            float* cc = acc[mf][nf];
            if (mode){
                int c0 = col % CD, c1 = (col + 1) % CD;
                const float* dk0 = g_dk + (size_t)row * CD;
                const float* dk8 = dk0 + 8 * CD;
                split_store(cc[0] * dk0[c0], g_Sh, g_Sl, (size_t)row*NC + col);
                split_store(cc[1] * dk0[c1], g_Sh, g_Sl, (size_t)row*NC + col + 1);
                split_store(cc[2] * dk8[c0], g_Sh, g_Sl, (size_t)(row+8)*NC + col);
                split_store(cc[3] * dk8[c1], g_Sh, g_Sl, (size_t)(row+8)*NC + col + 1);
            } else {
                g_U2[(size_t)row*NC + col]         = cc[0];
                g_U2[(size_t)row*NC + col + 1]     = cc[1];
                g_U2[(size_t)(row+8)*NC + col]     = cc[2];
                g_U2[(size_t)(row+8)*NC + col + 1] = cc[3];
            }
        }
    }
}

// ---------------- LayerNorm(C) * silu(z) ----------------
__global__ void k_ln(const float* __restrict__ gam, const float* __restrict__ bet){
    int row = blockIdx.x;                 // 0 .. BD*TD-1
    int b = row / TD, t = row - b * TD;
    int c = threadIdx.x;                  // 0 .. 191
    size_t base = (size_t)t * NC + (size_t)b * CD;

    float u = g_U2[base + c];
    float s1 = u, s2 = u * u;
    #pragma unroll
    for (int off = 16; off; off >>= 1){
        s1 += __shfl_xor_sync(0xffffffffu, s1, off);
        s2 += __shfl_xor_sync(0xffffffffu, s2, off);
    }
    __shared__ float sh[12];
    int w = c >> 5;
    if ((c & 31) == 0){ sh[w] = s1; sh[6 + w] = s2; }
    __syncthreads();
    float S1 = 0.f, S2 = 0.f;
    #pragma unroll
    for (int i = 0; i < 6; i++){ S1 += sh[i]; S2 += sh[6 + i]; }
    float mu  = S1 * (1.0f / CD);
    float var = S2 * (1.0f / CD) - mu * mu;
    float rs  = rsqrtf(var + 1e-5f);

    float z = g_Z[base + c];
    float sil = z / (1.f + expf(-z));
    g_G[base + c] = ((u - mu) * rs * gam[c] + bet[c]) * sil;
}

// ---------------- output depthwise conv + transpose to (B,T,C) ----------------
__global__ void k_outconv(const float* __restrict__ ow, const float* __restrict__ ob,
                          float* __restrict__ out){
    int idx = blockIdx.x * blockDim.x + threadIdx.x;  // BD*TD*CD
    int c = idx % CD;
    int tmp = idx / CD;
    int t = tmp % TD, b = tmp / TD;
    size_t bc = (size_t)b * CD + c;

    float a = ob[c] + g_G[(size_t)t * NC + bc] * ow[c*3 + 1];
    if (t > 0)      a += g_G[(size_t)(t-1) * NC + bc] * ow[c*3 + 0];
    if (t < TD-1)   a += g_G[(size_t)(t+1) * NC + bc] * ow[c*3 + 2];
    out[idx] = a;
}

// ---------------- launcher ----------------
extern "C" void kernel_launch(void* const* d_in, const int* in_sizes, int n_in,
                              void* d_out, int out_size){
    const float* x   = (const float*)d_in[0];
    const float* dw  = (const float*)d_in[1];
    const float* db  = (const float*)d_in[2];
    const float* lw  = (const float*)d_in[3];
    const float* lb  = (const float*)d_in[4];
    const float* gam = (const float*)d_in[5];
    const float* bet = (const float*)d_in[6];
    const float* ow  = (const float*)d_in[7];
    const float* ob  = (const float*)d_in[8];
    const float* kv  = (const float*)d_in[9];
    float* out = (float*)d_out;

    k_init_cos<<<(TD*TD)/256, 256>>>();
    {
        dim3 tb(32, 8), tg(TD/32, TD/32);
        k_transpose<<<tg, tb>>>();
    }
    k_init_dk <<<(TD*CD)/256, 256>>>(kv);
    {
        dim3 fg(TD/FT, BD);        // (128, 8)
        k_front<<<fg, 256>>>(x, dw, db, lw, lb);
    }

    dim3 gg(NC/BN, TD/BM);     // (24, 16)
    k_gemm<<<gg, 256>>>(1);    // A = Cos @ U, scale by decay^k, split
    k_gemm<<<gg, 256>>>(0);    // U2 = CosT @ A

    k_ln     <<<BD*TD, CD>>>(gam, bet);
    k_outconv<<<(BD*TD*CD)/256, 256>>>(ow, ob, out);
}